// round 8
// baseline (speedup 1.0000x reference)
#include <cuda_runtime.h>
#include <cstdint>

// ---------------------------------------------------------------------------
// Problem constants (fixed by the reference)
// ---------------------------------------------------------------------------
constexpr int Bn  = 4;
constexpr int Hh  = 192;
constexpr int Ww  = 192;
constexpr int HW  = Hh * Ww;          // 36864
constexpr int PIX = Bn * HW;          // 147456
constexpr int CIN = 64;
constexpr int CB  = 16;
constexpr int CM  = 256;              // num_colors == CM here
constexpr int BPB = HW / 256;         // pixel chunks of 256 per batch = 144
constexpr int HW4 = HW / 4;           // 9216 float4s per image plane

// Output layout: [transformed_img | m_sp | palette]
constexpr int OFF_T = 0;
constexpr int OFF_M = Bn * 3 * HW;
constexpr int OFF_P = OFF_M + Bn * CM * HW;

// ---------------------------------------------------------------------------
// Scratch (no allocations allowed -> device globals)
// ---------------------------------------------------------------------------
__device__ float    g_x[Bn * CB * HW];        // bottleneck pre-BN activations
__device__ unsigned g_keys[(size_t)PIX * 16]; // per-pixel packed (idx<<24 | sm_bits>>8)
__device__ float    g_bnsum[CB];
__device__ float    g_bnsq[CB];
__device__ float    g_scale[CB];
__device__ float    g_shift[CB];
__device__ float    g_num[Bn * 3 * CM];
__device__ float    g_den[Bn * CM];

// ---------------------------------------------------------------------------
// Kernel Z: zero the reduction scratch (graph replays reuse globals)
// ---------------------------------------------------------------------------
__global__ void kZero() {
    int t = threadIdx.x;
    for (int i = t; i < CB; i += 256)       { g_bnsum[i] = 0.f; g_bnsq[i] = 0.f; }
    for (int i = t; i < Bn * 3 * CM; i += 256) g_num[i] = 0.f;
    for (int i = t; i < Bn * CM; i += 256)     g_den[i] = 0.f;
}

// ---------------------------------------------------------------------------
// Kernel A: bottleneck 1x1 conv (64->16) + BN statistics
// 4 pixels per thread, float4 loads/stores. grid = 144 blocks x 256 threads.
// ---------------------------------------------------------------------------
__global__ __launch_bounds__(256) void kBneck(const float* __restrict__ bf,
                                              const float* __restrict__ wb,
                                              const float* __restrict__ bb) {
    __shared__ float wsh[CIN * CB];   // [c][o]
    __shared__ float sb[CB];
    __shared__ float ssum[CB], ssq[CB];

    int tid = threadIdx.x;
    for (int i = tid; i < CIN * CB; i += 256) {
        int o = i / CIN, c = i % CIN;
        wsh[c * CB + o] = wb[i];
    }
    if (tid < CB) { sb[tid] = bb[tid]; ssum[tid] = 0.f; ssq[tid] = 0.f; }
    __syncthreads();

    int t = blockIdx.x * 256 + tid;       // 0 .. 36863, one float4-of-pixels each
    int b = t / HW4;
    int r = t % HW4;

    float4 acc[CB];
#pragma unroll
    for (int o = 0; o < CB; o++) {
        float bv = sb[o];
        acc[o] = make_float4(bv, bv, bv, bv);
    }

    const float4* bf4 = reinterpret_cast<const float4*>(bf) + (size_t)b * CIN * HW4 + r;
#pragma unroll 4
    for (int c = 0; c < CIN; c++) {
        float4 v = bf4[(size_t)c * HW4];
#pragma unroll
        for (int o = 0; o < CB; o++) {
            float w = wsh[c * CB + o];
            acc[o].x = fmaf(v.x, w, acc[o].x);
            acc[o].y = fmaf(v.y, w, acc[o].y);
            acc[o].z = fmaf(v.z, w, acc[o].z);
            acc[o].w = fmaf(v.w, w, acc[o].w);
        }
    }

    float4* xp = reinterpret_cast<float4*>(g_x) + (size_t)b * CB * HW4 + r;
#pragma unroll
    for (int o = 0; o < CB; o++) xp[(size_t)o * HW4] = acc[o];

    int lane = tid & 31;
#pragma unroll
    for (int o = 0; o < CB; o++) {
        float4 a = acc[o];
        float s = a.x + a.y + a.z + a.w;
        float q = a.x * a.x + a.y * a.y + a.z * a.z + a.w * a.w;
#pragma unroll
        for (int off = 16; off > 0; off >>= 1) {
            s += __shfl_xor_sync(0xffffffffu, s, off);
            q += __shfl_xor_sync(0xffffffffu, q, off);
        }
        if (lane == 0) {
            atomicAdd(&ssum[o], s);
            atomicAdd(&ssq[o], q);
        }
    }
    __syncthreads();
    if (tid < CB) {
        atomicAdd(&g_bnsum[tid], ssum[tid]);
        atomicAdd(&g_bnsq[tid], ssq[tid]);
    }
}

// ---------------------------------------------------------------------------
// Kernel B: fold BN into scale/shift
// ---------------------------------------------------------------------------
__global__ void kBNFold(const float* __restrict__ gamma,
                        const float* __restrict__ beta) {
    int t = threadIdx.x;
    if (t < CB) {
        const float n = (float)PIX;
        float mean = g_bnsum[t] / n;
        float var  = g_bnsq[t] / n - mean * mean;
        float sc   = gamma[t] * rsqrtf(var + 1e-5f);
        g_scale[t] = sc;
        g_shift[t] = beta[t] - mean * sc;
    }
}

// value-only compare-exchange: ascending. 2 instructions (FMNMX x2).
#define CE2(A, x, y) { float lo_ = fminf(A[x], A[y]);             \
                       A[y] = fmaxf(A[x], A[y]); A[x] = lo_; }

// Batcher odd-even sort of 8 values (ascending), 19 CEs
#define SORT8V(V)                                                     \
    CE2(V, 0, 1) CE2(V, 2, 3) CE2(V, 4, 5) CE2(V, 6, 7)               \
    CE2(V, 0, 2) CE2(V, 1, 3) CE2(V, 4, 6) CE2(V, 5, 7)               \
    CE2(V, 1, 2) CE2(V, 5, 6)                                         \
    CE2(V, 0, 4) CE2(V, 1, 5) CE2(V, 2, 6) CE2(V, 3, 7)               \
    CE2(V, 2, 4) CE2(V, 3, 5)                                         \
    CE2(V, 1, 2) CE2(V, 3, 4) CE2(V, 5, 6)

// bitonic merge of 16 values (input bitonic) -> ascending, 32 CEs
#define BMERGE16V(V)                                                  \
    { _Pragma("unroll") for (int i_ = 0; i_ < 8; i_++)  CE2(V, i_, i_ + 8)   \
      _Pragma("unroll") for (int g_ = 0; g_ < 16; g_ += 8)            \
          _Pragma("unroll") for (int i_ = 0; i_ < 4; i_++)            \
              CE2(V, g_ + i_, g_ + i_ + 4)                            \
      _Pragma("unroll") for (int g_ = 0; g_ < 16; g_ += 4)            \
          _Pragma("unroll") for (int i_ = 0; i_ < 2; i_++)            \
              CE2(V, g_ + i_, g_ + i_ + 2)                            \
      _Pragma("unroll") for (int g_ = 0; g_ < 16; g_ += 2) CE2(V, g_, g_ + 1) }

// ---------------------------------------------------------------------------
// Kernel C: fused BN+ReLU -> mask GEMM (16->256) -> value-only top-16 (pass1,
//           logits spilled to local) -> exact index recovery (pass2) ->
//           softmax -> zero-fill + scatter m_sp -> palette accumulation
// ---------------------------------------------------------------------------
__global__ __launch_bounds__(256, 4) void kMask(const float* __restrict__ img,
                                                const float* __restrict__ wmask,
                                                float* __restrict__ out) {
    __shared__ __align__(16) float wm[CB * CM];   // transposed: wm[c*CM + k]
    __shared__ float snum[3 * CM];
    __shared__ float sden[CM];
    __shared__ float ssc[CB], ssh[CB];

    int tid = threadIdx.x;
    for (int i = tid; i < CB * CM; i += 256) {
        int k = i >> 4, c = i & 15;
        wm[c * CM + k] = wmask[i];
    }
    for (int i = tid; i < 3 * CM; i += 256) snum[i] = 0.f;
    for (int i = tid; i < CM; i += 256)     sden[i] = 0.f;
    if (tid < CB) { ssc[tid] = g_scale[tid]; ssh[tid] = g_shift[tid]; }
    __syncthreads();

    int b     = blockIdx.x / BPB;
    int chunk = blockIdx.x % BPB;
    int p     = chunk * 256 + tid;
    int gp    = b * HW + p;

    // m_sp zero-fill up front: stores drain underneath the ALU-heavy compute
    {
        float4* z4 = reinterpret_cast<float4*>(out + OFF_M + (size_t)b * CM * HW
                                               + (size_t)chunk * 256);
        const float4 zz = make_float4(0.f, 0.f, 0.f, 0.f);
#pragma unroll 8
        for (int j = tid; j < CM * 64; j += 256) {
            int k = j >> 6, q = j & 63;
            z4[(size_t)k * (HW / 4) + q] = zz;
        }
    }

    // BN + ReLU -> feat[16]
    float feat[CB];
    const float* xp = g_x + (size_t)b * CB * HW + p;
#pragma unroll
    for (int c = 0; c < CB; c++) {
        float xv = xp[(size_t)c * HW];
        feat[c] = fmaxf(fmaf(xv, ssc[c], ssh[c]), 0.f);
    }

    const float4* wmv = reinterpret_cast<const float4*>(wm);

#define GEMM8(NV, K0)                                                   \
    { _Pragma("unroll") for (int j_ = 0; j_ < 8; j_++) NV[j_] = 0.f;    \
      _Pragma("unroll") for (int c_ = 0; c_ < CB; c_++) {               \
          float f_ = feat[c_];                                          \
          int base_ = (c_ * CM + (K0)) >> 2;                            \
          float4 wA_ = wmv[base_];                                      \
          float4 wB_ = wmv[base_ + 1];                                  \
          NV[0] = fmaf(f_, wA_.x, NV[0]);                               \
          NV[1] = fmaf(f_, wA_.y, NV[1]);                               \
          NV[2] = fmaf(f_, wA_.z, NV[2]);                               \
          NV[3] = fmaf(f_, wA_.w, NV[3]);                               \
          NV[4] = fmaf(f_, wB_.x, NV[4]);                               \
          NV[5] = fmaf(f_, wB_.y, NV[5]);                               \
          NV[6] = fmaf(f_, wB_.z, NV[6]);                               \
          NV[7] = fmaf(f_, wB_.w, NV[7]);                               \
      } }

    float lg[CM];          // per-thread logit spill (local memory, 1 KB)

    // -------- pass 1: values-only streaming top-16 -------------------------
    float sv[16];
    {
        float nv[8];
        GEMM8(nv, 0)
#pragma unroll
        for (int j = 0; j < 8; j++) lg[j] = nv[j];
        SORT8V(nv)
        float mv[8];
        GEMM8(mv, 8)
#pragma unroll
        for (int j = 0; j < 8; j++) lg[8 + j] = mv[j];
        SORT8V(mv)
#pragma unroll
        for (int i = 0; i < 8; i++) { sv[i] = nv[i]; sv[8 + i] = mv[7 - i]; }
        BMERGE16V(sv)      // bitonic -> ascending
    }

#pragma unroll 1
    for (int k0 = 16; k0 < CM; k0 += 8) {
        float nv[8];
        GEMM8(nv, k0)
#pragma unroll
        for (int j = 0; j < 8; j++) lg[k0 + j] = nv[j];
        SORT8V(nv)
        // keep top-16 of (sv ∪ nv); result bitonic, then re-ascend
#pragma unroll
        for (int i = 0; i < 8; i++) sv[i] = fmaxf(sv[i], nv[7 - i]);
        BMERGE16V(sv)
    }

    float T    = sv[0];    // exact 16th-largest
    float vmax = sv[15];   // exact max

    // -------- pass 2: exact index recovery, k-ascending, cap 16 ------------
    // (cap reproduces JAX's smallest-index tie-break; guards the degenerate
    //  all-tied pixel where every logit is identical)
    float bv[16];
    int   bk[16];
#pragma unroll
    for (int i = 0; i < 16; i++) { bv[i] = 0.f; bk[i] = 0; }
    int cnt = 0;
    const float4* lg4 = reinterpret_cast<const float4*>(lg);
#pragma unroll 4
    for (int k4 = 0; k4 < CM / 4; k4++) {
        float4 v = lg4[k4];
        int k = k4 * 4;
        if (v.x >= T && cnt < 16) { bv[cnt] = v.x; bk[cnt] = k;     cnt++; }
        if (v.y >= T && cnt < 16) { bv[cnt] = v.y; bk[cnt] = k + 1; cnt++; }
        if (v.z >= T && cnt < 16) { bv[cnt] = v.z; bk[cnt] = k + 2; cnt++; }
        if (v.w >= T && cnt < 16) { bv[cnt] = v.w; bk[cnt] = k + 3; cnt++; }
    }

    // -------- softmax over the 16 selected (TEMP = 1) ----------------------
    float s = 0.f;
#pragma unroll
    for (int i = 0; i < 16; i++) { bv[i] = __expf(bv[i] - vmax); s += bv[i]; }
    float inv = 1.0f / s;
#pragma unroll
    for (int i = 0; i < 16; i++) bv[i] *= inv;

    __syncthreads();   // zero-fill (cross-thread) must land before scatter

    float* mo = out + OFF_M + (size_t)b * CM * HW + p;
#pragma unroll
    for (int i = 0; i < 16; i++) mo[(size_t)bk[i] * HW] = bv[i];

    // palette accumulation (full-precision sm) + compact key dump for recon
    float ir = img[((size_t)b * 3 + 0) * HW + p];
    float ig = img[((size_t)b * 3 + 1) * HW + p];
    float il = img[((size_t)b * 3 + 2) * HW + p];
#pragma unroll
    for (int i = 0; i < 16; i++) {
        atomicAdd(&sden[bk[i]], bv[i]);
        atomicAdd(&snum[bk[i]],          bv[i] * ir);
        atomicAdd(&snum[CM + bk[i]],     bv[i] * ig);
        atomicAdd(&snum[2 * CM + bk[i]], bv[i] * il);
        g_keys[(size_t)i * PIX + gp] =
            ((unsigned)bk[i] << 24) | (__float_as_uint(bv[i]) >> 8);
    }

    __syncthreads();
    for (int i = tid; i < 3 * CM; i += 256) atomicAdd(&g_num[b * 3 * CM + i], snum[i]);
    for (int i = tid; i < CM; i += 256)     atomicAdd(&g_den[b * CM + i],     sden[i]);
}

// ---------------------------------------------------------------------------
// Kernel D: finalize palette
// ---------------------------------------------------------------------------
__global__ void kPalette(float* __restrict__ out) {
    int t = blockIdx.x * blockDim.x + threadIdx.x;
    if (t < Bn * CM) {
        int b = t / CM, k = t % CM;
        float inv = 1.f / (g_den[t] + 1e-8f);
#pragma unroll
        for (int c = 0; c < 3; c++) {
            out[OFF_P + b * 3 * CM + c * CM + k] = g_num[b * 3 * CM + c * CM + k] * inv;
        }
    }
}

// ---------------------------------------------------------------------------
// Kernel E: transformed_img from compact keys + palette
// ---------------------------------------------------------------------------
__global__ __launch_bounds__(256) void kRecon(float* __restrict__ out) {
    __shared__ float pal[3 * CM];
    int tid   = threadIdx.x;
    int b     = blockIdx.x / BPB;
    int chunk = blockIdx.x % BPB;
    for (int i = tid; i < 3 * CM; i += 256) pal[i] = out[OFF_P + b * 3 * CM + i];
    __syncthreads();

    int p  = chunk * 256 + tid;
    int gp = b * HW + p;
    float a0 = 0.f, a1 = 0.f, a2 = 0.f;
#pragma unroll
    for (int i = 0; i < 16; i++) {
        unsigned u = g_keys[(size_t)i * PIX + gp];
        int idx = u >> 24;
        float sm = __uint_as_float((u & 0x00FFFFFFu) << 8);
        a0 = fmaf(sm, pal[idx], a0);
        a1 = fmaf(sm, pal[CM + idx], a1);
        a2 = fmaf(sm, pal[2 * CM + idx], a2);
    }
    out[OFF_T + ((size_t)b * 3 + 0) * HW + p] = a0;
    out[OFF_T + ((size_t)b * 3 + 1) * HW + p] = a1;
    out[OFF_T + ((size_t)b * 3 + 2) * HW + p] = a2;
}

// ---------------------------------------------------------------------------
// Launch
// ---------------------------------------------------------------------------
extern "C" void kernel_launch(void* const* d_in, const int* in_sizes, int n_in,
                              void* d_out, int out_size) {
    const float* img   = (const float*)d_in[0];
    const float* bfeat = (const float*)d_in[1];
    const float* wb    = (const float*)d_in[2];
    const float* bb    = (const float*)d_in[3];
    const float* gam   = (const float*)d_in[4];
    const float* bet   = (const float*)d_in[5];
    const float* wmask = (const float*)d_in[6];
    float* out = (float*)d_out;

    const int grid = Bn * BPB;  // 576

    kZero<<<1, 256>>>();
    kBneck<<<PIX / 4 / 256, 256>>>(bfeat, wb, bb);
    kBNFold<<<1, 32>>>(gam, bet);
    kMask<<<grid, 256>>>(img, wmask, out);
    kPalette<<<(Bn * CM + 255) / 256, 256>>>(out);
    kRecon<<<grid, 256>>>(out);
}

// round 9
// speedup vs baseline: 1.0566x; 1.0566x over previous
#include <cuda_runtime.h>
#include <cstdint>

// ---------------------------------------------------------------------------
// Problem constants (fixed by the reference)
// ---------------------------------------------------------------------------
constexpr int Bn  = 4;
constexpr int Hh  = 192;
constexpr int Ww  = 192;
constexpr int HW  = Hh * Ww;          // 36864
constexpr int PIX = Bn * HW;          // 147456
constexpr int CIN = 64;
constexpr int CB  = 16;
constexpr int CM  = 256;              // num_colors == CM here
constexpr int BPB = HW / 256;         // pixel chunks of 256 per batch = 144

// Output layout: [transformed_img | m_sp | palette]
constexpr int OFF_T = 0;
constexpr int OFF_M = Bn * 3 * HW;
constexpr int OFF_P = OFF_M + Bn * CM * HW;

// ---------------------------------------------------------------------------
// Scratch (no allocations allowed -> device globals)
// ---------------------------------------------------------------------------
__device__ float    g_x[Bn * CB * HW];        // bottleneck pre-BN activations
__device__ unsigned g_keys[(size_t)PIX * 16]; // per-pixel packed (idx<<24 | sm_bits>>8)
__device__ float    g_bnsum[CB];
__device__ float    g_bnsq[CB];
__device__ float    g_scale[CB];
__device__ float    g_shift[CB];
__device__ float    g_num[Bn * 3 * CM];
__device__ float    g_den[Bn * CM];

// ---------------------------------------------------------------------------
// f32x2 helpers (Blackwell packed fp32: 2 MACs per instruction)
// ---------------------------------------------------------------------------
__device__ __forceinline__ unsigned long long ffma2(unsigned long long a,
                                                    unsigned long long b,
                                                    unsigned long long c) {
    unsigned long long r;
    asm("fma.rn.f32x2 %0, %1, %2, %3;" : "=l"(r) : "l"(a), "l"(b), "l"(c));
    return r;
}
__device__ __forceinline__ unsigned long long pack2(float lo, float hi) {
    unsigned long long r;
    asm("mov.b64 %0, {%1, %2};" : "=l"(r) : "f"(lo), "f"(hi));
    return r;
}
__device__ __forceinline__ void unpack2(unsigned long long p, float& lo, float& hi) {
    asm("mov.b64 {%0, %1}, %2;" : "=f"(lo), "=f"(hi) : "l"(p));
}

// ---------------------------------------------------------------------------
// Kernel Z: zero the reduction scratch (graph replays reuse globals)
// ---------------------------------------------------------------------------
__global__ void kZero() {
    int t = threadIdx.x;
    for (int i = t; i < CB; i += 256)       { g_bnsum[i] = 0.f; g_bnsq[i] = 0.f; }
    for (int i = t; i < Bn * 3 * CM; i += 256) g_num[i] = 0.f;
    for (int i = t; i < Bn * CM; i += 256)     g_den[i] = 0.f;
}

// ---------------------------------------------------------------------------
// Kernel A: bottleneck 1x1 conv (64->16, exact fp32) + BN statistics
// (reverted to the validated R6 version)
// ---------------------------------------------------------------------------
__global__ __launch_bounds__(256) void kBneck(const float* __restrict__ bf,
                                              const float* __restrict__ wb,
                                              const float* __restrict__ bb) {
    __shared__ __align__(16) float wsh[CIN * CB];   // [c][o]
    __shared__ float sb[CB];
    __shared__ float ssum[CB], ssq[CB];

    int tid = threadIdx.x;
    for (int i = tid; i < CIN * CB; i += 256) {
        int o = i / CIN, c = i % CIN;
        wsh[c * CB + o] = wb[i];
    }
    if (tid < CB) { sb[tid] = bb[tid]; ssum[tid] = 0.f; ssq[tid] = 0.f; }
    __syncthreads();

    int b     = blockIdx.x / BPB;
    int chunk = blockIdx.x % BPB;
    int p     = chunk * 256 + tid;

    float acc[CB];
#pragma unroll
    for (int o = 0; o < CB; o++) acc[o] = sb[o];

    const float* bfp = bf + (size_t)b * CIN * HW + p;
    const float4* w4 = reinterpret_cast<const float4*>(wsh);
#pragma unroll 4
    for (int c = 0; c < CIN; c++) {
        float v = bfp[(size_t)c * HW];
#pragma unroll
        for (int q = 0; q < 4; q++) {
            float4 w = w4[c * 4 + q];
            acc[q * 4 + 0] = fmaf(v, w.x, acc[q * 4 + 0]);
            acc[q * 4 + 1] = fmaf(v, w.y, acc[q * 4 + 1]);
            acc[q * 4 + 2] = fmaf(v, w.z, acc[q * 4 + 2]);
            acc[q * 4 + 3] = fmaf(v, w.w, acc[q * 4 + 3]);
        }
    }

    float* xp = g_x + (size_t)b * CB * HW + p;
#pragma unroll
    for (int o = 0; o < CB; o++) xp[(size_t)o * HW] = acc[o];

    int lane = tid & 31;
#pragma unroll
    for (int o = 0; o < CB; o++) {
        float s = acc[o];
        float q = acc[o] * acc[o];
#pragma unroll
        for (int off = 16; off > 0; off >>= 1) {
            s += __shfl_xor_sync(0xffffffffu, s, off);
            q += __shfl_xor_sync(0xffffffffu, q, off);
        }
        if (lane == 0) {
            atomicAdd(&ssum[o], s);
            atomicAdd(&ssq[o], q);
        }
    }
    __syncthreads();
    if (tid < CB) {
        atomicAdd(&g_bnsum[tid], ssum[tid]);
        atomicAdd(&g_bnsq[tid], ssq[tid]);
    }
}

// ---------------------------------------------------------------------------
// Kernel B: fold BN into scale/shift
// ---------------------------------------------------------------------------
__global__ void kBNFold(const float* __restrict__ gamma,
                        const float* __restrict__ beta) {
    int t = threadIdx.x;
    if (t < CB) {
        const float n = (float)PIX;
        float mean = g_bnsum[t] / n;
        float var  = g_bnsq[t] / n - mean * mean;
        float sc   = gamma[t] * rsqrtf(var + 1e-5f);
        g_scale[t] = sc;
        g_shift[t] = beta[t] - mean * sc;
    }
}

// value-only compare-exchange: ascending. 2 instructions (FMNMX x2).
#define CE2(A, x, y) { float lo_ = fminf(A[x], A[y]);             \
                       A[y] = fmaxf(A[x], A[y]); A[x] = lo_; }

// Batcher odd-even sort of 8 values (ascending), 19 CEs
#define SORT8V(V)                                                     \
    CE2(V, 0, 1) CE2(V, 2, 3) CE2(V, 4, 5) CE2(V, 6, 7)               \
    CE2(V, 0, 2) CE2(V, 1, 3) CE2(V, 4, 6) CE2(V, 5, 7)               \
    CE2(V, 1, 2) CE2(V, 5, 6)                                         \
    CE2(V, 0, 4) CE2(V, 1, 5) CE2(V, 2, 6) CE2(V, 3, 7)               \
    CE2(V, 2, 4) CE2(V, 3, 5)                                         \
    CE2(V, 1, 2) CE2(V, 3, 4) CE2(V, 5, 6)

// bitonic merge of 16 values (input bitonic) -> ascending, 32 CEs
#define BMERGE16V(V)                                                  \
    { _Pragma("unroll") for (int i_ = 0; i_ < 8; i_++)  CE2(V, i_, i_ + 8)   \
      _Pragma("unroll") for (int g_ = 0; g_ < 16; g_ += 8)            \
          _Pragma("unroll") for (int i_ = 0; i_ < 4; i_++)            \
              CE2(V, g_ + i_, g_ + i_ + 4)                            \
      _Pragma("unroll") for (int g_ = 0; g_ < 16; g_ += 4)            \
          _Pragma("unroll") for (int i_ = 0; i_ < 2; i_++)            \
              CE2(V, g_ + i_, g_ + i_ + 2)                            \
      _Pragma("unroll") for (int g_ = 0; g_ < 16; g_ += 2) CE2(V, g_, g_ + 1) }

// ---------------------------------------------------------------------------
// Kernel C: fused BN+ReLU -> f32x2 mask GEMM -> value-only top-16 (pass1)
//           -> GEMM recompute + exact index recovery (pass2, no spill)
//           -> softmax -> zero-fill + scatter m_sp -> palette accumulation
// ---------------------------------------------------------------------------
__global__ __launch_bounds__(256, 3) void kMask(const float* __restrict__ img,
                                                const float* __restrict__ wmask,
                                                float* __restrict__ out) {
    __shared__ __align__(16) float wm[CB * CM];   // transposed: wm[c*CM + k]
    __shared__ float snum[3 * CM];
    __shared__ float sden[CM];
    __shared__ float ssc[CB], ssh[CB];

    int tid = threadIdx.x;
    for (int i = tid; i < CB * CM; i += 256) {
        int k = i >> 4, c = i & 15;
        wm[c * CM + k] = wmask[i];
    }
    for (int i = tid; i < 3 * CM; i += 256) snum[i] = 0.f;
    for (int i = tid; i < CM; i += 256)     sden[i] = 0.f;
    if (tid < CB) { ssc[tid] = g_scale[tid]; ssh[tid] = g_shift[tid]; }
    __syncthreads();

    int b     = blockIdx.x / BPB;
    int chunk = blockIdx.x % BPB;
    int p     = chunk * 256 + tid;
    int gp    = b * HW + p;

    // m_sp zero-fill up front: stores drain underneath the ALU-heavy compute
    {
        float4* z4 = reinterpret_cast<float4*>(out + OFF_M + (size_t)b * CM * HW
                                               + (size_t)chunk * 256);
        const float4 zz = make_float4(0.f, 0.f, 0.f, 0.f);
#pragma unroll 8
        for (int j = tid; j < CM * 64; j += 256) {
            int k = j >> 6, q = j & 63;
            z4[(size_t)k * (HW / 4) + q] = zz;
        }
    }

    // BN + ReLU -> feat, pre-packed as (f,f) f32x2 pairs
    unsigned long long featp[CB];
    const float* xp = g_x + (size_t)b * CB * HW + p;
#pragma unroll
    for (int c = 0; c < CB; c++) {
        float xv = xp[(size_t)c * HW];
        float f  = fmaxf(fmaf(xv, ssc[c], ssh[c]), 0.f);
        featp[c] = pack2(f, f);
    }

    // f32x2 GEMM for one 8-output group; identical FMA chain both passes
    // (bit-deterministic, so pass-2 values equal pass-1 values exactly)
#define GEMM8P(NV, K0)                                                          \
    { unsigned long long a0_ = 0ULL, a1_ = 0ULL, a2_ = 0ULL, a3_ = 0ULL;        \
      _Pragma("unroll") for (int c_ = 0; c_ < CB; c_++) {                       \
          const ulonglong2* wp_ =                                               \
              reinterpret_cast<const ulonglong2*>(wm + c_ * CM + (K0));         \
          ulonglong2 wA_ = wp_[0];                                              \
          ulonglong2 wB_ = wp_[1];                                              \
          a0_ = ffma2(featp[c_], wA_.x, a0_);                                   \
          a1_ = ffma2(featp[c_], wA_.y, a1_);                                   \
          a2_ = ffma2(featp[c_], wB_.x, a2_);                                   \
          a3_ = ffma2(featp[c_], wB_.y, a3_);                                   \
      }                                                                         \
      unpack2(a0_, NV[0], NV[1]); unpack2(a1_, NV[2], NV[3]);                   \
      unpack2(a2_, NV[4], NV[5]); unpack2(a3_, NV[6], NV[7]); }

    // -------- pass 1: values-only streaming top-16 -------------------------
    float sv[16];
    {
        float nv[8];
        GEMM8P(nv, 0)
        SORT8V(nv)
        float mv[8];
        GEMM8P(mv, 8)
        SORT8V(mv)
#pragma unroll
        for (int i = 0; i < 8; i++) { sv[i] = nv[i]; sv[8 + i] = mv[7 - i]; }
        BMERGE16V(sv)      // bitonic -> ascending
    }

#pragma unroll 1
    for (int k0 = 16; k0 < CM; k0 += 8) {
        float nv[8];
        GEMM8P(nv, k0)
        SORT8V(nv)
#pragma unroll
        for (int i = 0; i < 8; i++) sv[i] = fmaxf(sv[i], nv[7 - i]);
        BMERGE16V(sv)
    }

    float T    = sv[0];    // exact 16th-largest
    float vmax = sv[15];   // exact max

    // -------- pass 2: GEMM recompute + exact index recovery ----------------
    // k-ascending push capped at 16 == JAX smallest-index tie-break (also
    // covers the degenerate all-tied pixel). Values bit-identical to pass 1.
    float bv[16];
    int   bk[16];
#pragma unroll
    for (int i = 0; i < 16; i++) { bv[i] = 0.f; bk[i] = 0; }
    int cnt = 0;
#pragma unroll 1
    for (int k0 = 0; k0 < CM; k0 += 8) {
        float nv[8];
        GEMM8P(nv, k0)
#pragma unroll
        for (int j = 0; j < 8; j++) {
            if (nv[j] >= T && cnt < 16) { bv[cnt] = nv[j]; bk[cnt] = k0 + j; cnt++; }
        }
    }

    // -------- softmax over the 16 selected (TEMP = 1) ----------------------
    float s = 0.f;
#pragma unroll
    for (int i = 0; i < 16; i++) { bv[i] = __expf(bv[i] - vmax); s += bv[i]; }
    float inv = 1.0f / s;
#pragma unroll
    for (int i = 0; i < 16; i++) bv[i] *= inv;

    __syncthreads();   // zero-fill (cross-thread) must land before scatter

    float* mo = out + OFF_M + (size_t)b * CM * HW + p;
#pragma unroll
    for (int i = 0; i < 16; i++) mo[(size_t)bk[i] * HW] = bv[i];

    // palette accumulation (full-precision sm) + compact key dump for recon
    float ir = img[((size_t)b * 3 + 0) * HW + p];
    float ig = img[((size_t)b * 3 + 1) * HW + p];
    float il = img[((size_t)b * 3 + 2) * HW + p];
#pragma unroll
    for (int i = 0; i < 16; i++) {
        atomicAdd(&sden[bk[i]], bv[i]);
        atomicAdd(&snum[bk[i]],          bv[i] * ir);
        atomicAdd(&snum[CM + bk[i]],     bv[i] * ig);
        atomicAdd(&snum[2 * CM + bk[i]], bv[i] * il);
        g_keys[(size_t)i * PIX + gp] =
            ((unsigned)bk[i] << 24) | (__float_as_uint(bv[i]) >> 8);
    }

    __syncthreads();
    for (int i = tid; i < 3 * CM; i += 256) atomicAdd(&g_num[b * 3 * CM + i], snum[i]);
    for (int i = tid; i < CM; i += 256)     atomicAdd(&g_den[b * CM + i],     sden[i]);
}

// ---------------------------------------------------------------------------
// Kernel D: finalize palette
// ---------------------------------------------------------------------------
__global__ void kPalette(float* __restrict__ out) {
    int t = blockIdx.x * blockDim.x + threadIdx.x;
    if (t < Bn * CM) {
        int b = t / CM, k = t % CM;
        float inv = 1.f / (g_den[t] + 1e-8f);
#pragma unroll
        for (int c = 0; c < 3; c++) {
            out[OFF_P + b * 3 * CM + c * CM + k] = g_num[b * 3 * CM + c * CM + k] * inv;
        }
    }
}

// ---------------------------------------------------------------------------
// Kernel E: transformed_img from compact keys + palette
// ---------------------------------------------------------------------------
__global__ __launch_bounds__(256) void kRecon(float* __restrict__ out) {
    __shared__ float pal[3 * CM];
    int tid   = threadIdx.x;
    int b     = blockIdx.x / BPB;
    int chunk = blockIdx.x % BPB;
    for (int i = tid; i < 3 * CM; i += 256) pal[i] = out[OFF_P + b * 3 * CM + i];
    __syncthreads();

    int p  = chunk * 256 + tid;
    int gp = b * HW + p;
    float a0 = 0.f, a1 = 0.f, a2 = 0.f;
#pragma unroll
    for (int i = 0; i < 16; i++) {
        unsigned u = g_keys[(size_t)i * PIX + gp];
        int idx = u >> 24;
        float sm = __uint_as_float((u & 0x00FFFFFFu) << 8);
        a0 = fmaf(sm, pal[idx], a0);
        a1 = fmaf(sm, pal[CM + idx], a1);
        a2 = fmaf(sm, pal[2 * CM + idx], a2);
    }
    out[OFF_T + ((size_t)b * 3 + 0) * HW + p] = a0;
    out[OFF_T + ((size_t)b * 3 + 1) * HW + p] = a1;
    out[OFF_T + ((size_t)b * 3 + 2) * HW + p] = a2;
}

// ---------------------------------------------------------------------------
// Launch
// ---------------------------------------------------------------------------
extern "C" void kernel_launch(void* const* d_in, const int* in_sizes, int n_in,
                              void* d_out, int out_size) {
    const float* img   = (const float*)d_in[0];
    const float* bfeat = (const float*)d_in[1];
    const float* wb    = (const float*)d_in[2];
    const float* bb    = (const float*)d_in[3];
    const float* gam   = (const float*)d_in[4];
    const float* bet   = (const float*)d_in[5];
    const float* wmask = (const float*)d_in[6];
    float* out = (float*)d_out;

    const int grid = Bn * BPB;  // 576

    kZero<<<1, 256>>>();
    kBneck<<<grid, 256>>>(bfeat, wb, bb);
    kBNFold<<<1, 32>>>(gam, bet);
    kMask<<<grid, 256>>>(img, wmask, out);
    kPalette<<<(Bn * CM + 255) / 256, 256>>>(out);
    kRecon<<<grid, 256>>>(out);
}